// round 15
// baseline (speedup 1.0000x reference)
#include <cuda_runtime.h>
#include <cuda_bf16.h>
#include <cstdint>

// ---------------------------------------------------------------------------
// GCNArchEmbedder via mma.sync bf16 (HMMA), 3-pass hi/lo fp32 emulation.
// R15: SINGLE fused persistent kernel (R14 with the 512-thread prep indexing
//   bug fixed: step 1 is a grid-stride loop over all 864 T/Y entries).
//   Pipeline identical to R13 (best passing: 39.4us with separate prep).
// ---------------------------------------------------------------------------

#define NUM_PRIM   8
#define OPD        48
#define OPH        48
#define GD         128
#define ROWS       65536
#define TILE_M     64
#define NTILES     (ROWS / TILE_M)     // 1024
#define NCTAS      148
#define TPAD       132

typedef unsigned long long ull;
__device__ __forceinline__ ull pk2(float lo, float hi) {
    ull r; asm("mov.b64 %0, {%1, %2};" : "=l"(r) : "f"(lo), "f"(hi)); return r;
}
__device__ __forceinline__ void unpk2(float& lo, float& hi, ull v) {
    asm("mov.b64 {%0, %1}, %2;" : "=f"(lo), "=f"(hi) : "l"(v));
}
__device__ __forceinline__ ull add2(ull a, ull b) {
    ull r; asm("add.rn.f32x2 %0, %1, %2;" : "=l"(r) : "l"(a), "l"(b)); return r;
}
__device__ __forceinline__ ull mul2(ull a, ull b) {
    ull r; asm("mul.rn.f32x2 %0, %1, %2;" : "=l"(r) : "l"(a), "l"(b)); return r;
}
__device__ __forceinline__ void fma2(ull& d, ull a, ull b) {
    asm("fma.rn.f32x2 %0, %1, %2, %0;" : "+l"(d) : "l"(a), "l"(b));
}
// low half = first arg (k-even element)
__device__ __forceinline__ uint32_t bf16x2(float lo, float hi) {
    uint32_t r; asm("cvt.rn.bf16x2.f32 %0, %1, %2;" : "=r"(r) : "f"(hi), "f"(lo)); return r;
}
__device__ __forceinline__ float bf_lo(uint32_t u) { return __uint_as_float(u << 16); }
__device__ __forceinline__ float bf_hi(uint32_t u) { return __uint_as_float(u & 0xffff0000u); }

__device__ __forceinline__ void mma_bf16(float* d, const uint32_t* a,
                                         uint32_t b0, uint32_t b1) {
    asm volatile(
        "mma.sync.aligned.m16n8k16.row.col.f32.bf16.bf16.f32 "
        "{%0,%1,%2,%3}, {%4,%5,%6,%7}, {%8,%9}, {%0,%1,%2,%3};"
        : "+f"(d[0]), "+f"(d[1]), "+f"(d[2]), "+f"(d[3])
        : "r"(a[0]), "r"(a[1]), "r"(a[2]), "r"(a[3]), "r"(b0), "r"(b1));
}

// named-barrier produce/consume (count = all 512 threads)
#define BAR_SYNC(id)   asm volatile("bar.sync %0, 512;"   :: "r"(id) : "memory")
#define BAR_ARRIVE(id) asm volatile("bar.arrive %0, 512;" :: "r"(id) : "memory")
#define BAR_EMPTY0 1
#define BAR_EMPTY1 2
#define BAR_FULL0  3
#define BAR_FULL1  4

// ---------------------------------------------------------------------------
// smem byte layout:
//   AH[2]  0      (2 x 16384)   [g4][ks8][pos32] uint4, XOR-swizzled pos
//                 (staging scratch T[8][2][48] + Y[2][48] overlays this)
//   AL[2]  32768  (2 x 16384)
//   B      65536  (65536)       [ks8][nt16][lane32] uint4 {b0h,b1h,b0l,b1l}
//   tab    131072 (9504)        18 x TPAD floats
// total 140576 B -> 1 CTA/SM.
// ---------------------------------------------------------------------------
#define SM_AH    0
#define SM_AL    32768
#define SM_B     65536
#define SM_TAB   131072
#define SMEM_BYTES 140576

__global__ void __launch_bounds__(512, 1)
gcn_main_kernel(const int* __restrict__ archs,
                const float* __restrict__ init_emb,
                const float* __restrict__ op_emb,
                const float* __restrict__ xw,
                const float* __restrict__ xb,
                const float* __restrict__ w1,
                const float* __restrict__ w2,
                float* __restrict__ out) {
    extern __shared__ char smem[];
    float* tab = (float*)(smem + SM_TAB);

    const int tid  = threadIdx.x;
    const int wid  = tid >> 5;
    const int lane = tid & 31;
    const bool consumer = (wid < 8);

    // ===================== fused prep (per-CTA, staging) =====================
    {
        float* Tsc = (float*)(smem + SM_AH);   // [8][2][48] = 768 floats
        float* Ysc = Tsc + 768;                // [2][48]

        // step 1: T (xb folded into which==0 -> Uc emerges in step 2) and Y.
        // 864 entries total, grid-stride over 512 threads.
        for (int idx = tid; idx < 864; idx += 512) {
            if (idx < 768) {
                const int p = idx / 96;
                const int rem = idx % 96;
                const int which = rem / 48;
                const int h = rem % 48;
                float acc = (which == 0) ? xb[h] : 0.f;
                const int db = which * OPD;
                for (int d = 0; d < OPD; d += 2) {
                    acc = fmaf(op_emb[p * OPD + d],     xw[(db + d) * OPH + h],     acc);
                    acc = fmaf(op_emb[p * OPD + d + 1], xw[(db + d + 1) * OPH + h], acc);
                }
                Tsc[(p * 2 + which) * OPH + h] = acc;
            } else {
                const int kk = (idx - 768) / 48;
                const int h = (idx - 768) % 48;
                float acc = xb[h];
                for (int d = 0; d < 2 * OPD; d += 2) {
                    acc = fmaf(init_emb[kk * 2 * OPD + d],     xw[d * OPH + h],       acc);
                    acc = fmaf(init_emb[kk * 2 * OPD + d + 1], xw[(d + 1) * OPH + h], acc);
                }
                Ysc[kk * OPH + h] = acc;
            }
        }
        __syncthreads();

        // step 2: tab rows 0..7 = U0''[p] (incl. Uc), 8..15 = U1[p], 16..17 = H1init
        for (int idx = tid; idx < 18 * GD; idx += 512) {
            const int row = idx >> 7;
            const int f = idx & 127;
            const float* src = (row < 16) ? (Tsc + ((row & 7) * 2 + (row >> 3)) * OPH)
                                          : (Ysc + (row - 16) * OPH);
            float s0 = 0.f, s1 = 0.f;
            for (int h = 0; h < OPH; h += 2) {
                s0 = fmaf(src[h],     w1[h * GD + f],       s0);
                s1 = fmaf(src[h + 1], w1[(h + 1) * GD + f], s1);
            }
            tab[row * TPAD + f] = s0 + s1;
        }

        // step 3: W2 -> bf16 hi/lo mma B-fragments, written in-place
        uint4* Bsm = (uint4*)(smem + SM_B);
#pragma unroll
        for (int i = 0; i < 8; i++) {
            const int idx = tid + 512 * i;       // 0..4095
            const int bl  = idx & 31;
            const int nt  = (idx >> 5) & 15;
            const int ks  = idx >> 9;
            const int k0 = ks * 16 + (bl & 3) * 2;
            const int n  = nt * 8 + (bl >> 2);
            float w00 = w2[k0 * GD + n];
            float w01 = w2[(k0 + 1) * GD + n];
            float w10 = w2[(k0 + 8) * GD + n];
            float w11 = w2[(k0 + 9) * GD + n];
            uint32_t b0h = bf16x2(w00, w01);
            uint32_t b1h = bf16x2(w10, w11);
            uint32_t b0l = bf16x2(w00 - bf_lo(b0h), w01 - bf_hi(b0h));
            uint32_t b1l = bf16x2(w10 - bf_lo(b1h), w11 - bf_hi(b1h));
            Bsm[idx] = make_uint4(b0h, b1h, b0l, b1l);
        }
    }
    __syncthreads();

    // ===================== pipeline (verbatim R13) =====================
    // consumer constants
    const int rg = (wid >> 2) & 1;
    const int cg = wid & 3;
    const int pos = (lane & 28) | ((lane ^ (lane >> 3)) & 3);
    // producer constants
    const int ptid = tid - 256;
    const int prow = ptid & 63;
    const int pkq  = (ptid >> 6) & 3;

    // consumers pre-signal both buffers empty
    if (consumer) {
        BAR_ARRIVE(BAR_EMPTY0);
        BAR_ARRIVE(BAR_EMPTY1);
    }

    int parity = 0;
    for (int t = blockIdx.x; t < NTILES; t += NCTAS, parity ^= 1) {
        if (!consumer) {
            // ================= PRODUCE tile t into buf[parity] =================
            BAR_SYNC(parity ? BAR_EMPTY1 : BAR_EMPTY0);

            const int row = prow;
            const int g_  = row >> 4;
            const int r   = row & 7;
            const bool hiRole = ((row & 8) == 0);

            const int4* ap = (const int4*)(archs + ((size_t)t * TILE_M + row) * 16);
            int4 a0v = __ldg(ap), a1v = __ldg(ap + 1);
            int4 a2v = __ldg(ap + 2), a3v = __ldg(ap + 3);
            int pe[8] = {a0v.x, a0v.y, a0v.z, a0v.w, a1v.x, a1v.y, a1v.z, a1v.w};
            int oe[8] = {a2v.x, a2v.y, a2v.z, a2v.w, a3v.x, a3v.y, a3v.z, a3v.w};

            ull A2[4][6];
            float mmv[4];
#pragma unroll
            for (int s = 0; s < 4; s++) {
#pragma unroll
                for (int j = 0; j < 6; j++) {
                    float v = (pe[2 * s] == j ? 1.f : 0.f) + (pe[2 * s + 1] == j ? 1.f : 0.f);
                    A2[s][j] = pk2(v, v);
                }
                float c = 0.f;
#pragma unroll
                for (int e = 0; e < 8; e++) c += (pe[e] == s + 2) ? 1.f : 0.f;
                mmv[s] = c * 0.25f;
            }

            const float* qa0 = tab + oe[0] * TPAD;
            const float* qb0 = tab + (8 + oe[1]) * TPAD;
            const float* qa1 = tab + oe[2] * TPAD;
            const float* qb1 = tab + (8 + oe[3]) * TPAD;
            const float* qa2 = tab + oe[4] * TPAD;
            const float* qb2 = tab + (8 + oe[5]) * TPAD;
            const float* qa3 = tab + oe[6] * TPAD;
            const float* qb3 = tab + (8 + oe[7]) * TPAD;
            const float* p0 = tab + 16 * TPAD;
            const float* p1 = tab + 17 * TPAD;

            // quadcomp: one float4 batch -> TWO k-pair results (hi2/lo2 [0..1])
            auto quadcomp = [&](int k, uint32_t* hi2, uint32_t* lo2) {
                ulonglong2 H0 = *(const ulonglong2*)(p0 + k);
                ulonglong2 H1 = *(const ulonglong2*)(p1 + k);
                ulonglong2 QA0 = *(const ulonglong2*)(qa0 + k);
                ulonglong2 QB0 = *(const ulonglong2*)(qb0 + k);
                ulonglong2 QA1 = *(const ulonglong2*)(qa1 + k);
                ulonglong2 QB1 = *(const ulonglong2*)(qb1 + k);
                ulonglong2 QA2 = *(const ulonglong2*)(qa2 + k);
                ulonglong2 QB2 = *(const ulonglong2*)(qb2 + k);
                ulonglong2 QA3 = *(const ulonglong2*)(qa3 + k);
                ulonglong2 QB3 = *(const ulonglong2*)(qb3 + k);
                ull h[6][2];
                h[0][0] = H0.x; h[0][1] = H0.y;
                h[1][0] = H1.x; h[1][1] = H1.y;
                h[2][0] = add2(QA0.x, QB0.x); h[2][1] = add2(QA0.y, QB0.y);
                h[3][0] = add2(QA1.x, QB1.x); h[3][1] = add2(QA1.y, QB1.y);
                h[4][0] = add2(QA2.x, QB2.x); h[4][1] = add2(QA2.y, QB2.y);
                h[5][0] = add2(QA3.x, QB3.x); h[5][1] = add2(QA3.y, QB3.y);
#pragma unroll
                for (int u = 0; u < 2; u++) {
                    float s0 = 0.f, s1 = 0.f;
#pragma unroll
                    for (int s = 0; s < 4; s++) {
                        ull z = mul2(A2[s][0], h[0][u]);
                        fma2(z, A2[s][1], h[1][u]);
                        fma2(z, A2[s][2], h[2][u]);
                        fma2(z, A2[s][3], h[3][u]);
                        fma2(z, A2[s][4], h[4][u]);
                        fma2(z, A2[s][5], h[5][u]);
                        float zl, zh; unpk2(zl, zh, z);
                        zl = fmaxf(zl, 0.f);
                        zh = fmaxf(zh, 0.f);
                        s0 = fmaf(mmv[s], zl, s0);
                        s1 = fmaf(mmv[s], zh, s1);
                    }
                    hi2[u] = bf16x2(s0, s1);
                    lo2[u] = bf16x2(s0 - bf_lo(hi2[u]), s1 - bf_hi(hi2[u]));
                }
            };

            char* bufH = smem + SM_AH + parity * 16384;
            char* bufL = smem + SM_AL + parity * 16384;
#pragma unroll
            for (int kk = 0; kk < 2; kk++) {
                const int ks = pkq * 2 + kk;
                char* slotH = bufH + (g_ * 8 + ks) * 512;
                char* slotL = bufL + (g_ * 8 + ks) * 512;
#pragma unroll
                for (int jj = 0; jj < 2; jj++) {
                    uint32_t hA[2], lA[2], hC[2], lC[2];
                    quadcomp(ks * 16 + 4 * jj, hA, lA);
                    quadcomp(ks * 16 + 8 + 4 * jj, hC, lC);
#pragma unroll
                    for (int u = 0; u < 2; u++) {
                        const int j = 2 * jj + u;
                        uint32_t ohA = __shfl_xor_sync(0xffffffffu, hA[u], 8);
                        uint32_t ohC = __shfl_xor_sync(0xffffffffu, hC[u], 8);
                        uint32_t olA = __shfl_xor_sync(0xffffffffu, lA[u], 8);
                        uint32_t olC = __shfl_xor_sync(0xffffffffu, lC[u], 8);
                        const int p_ = r * 4 + (j ^ ((r >> 1) & 3));
                        if (hiRole) {
                            *(uint4*)(slotH + p_ * 16) = make_uint4(hA[u], ohA, hC[u], ohC);
                        } else {
                            *(uint4*)(slotL + p_ * 16) = make_uint4(olA, lA[u], olC, lC[u]);
                        }
                    }
                }
            }
            BAR_ARRIVE(parity ? BAR_FULL1 : BAR_FULL0);
        } else {
            // ================= CONSUME tile t from buf[parity] =================
            BAR_SYNC(parity ? BAR_FULL1 : BAR_FULL0);

            const char* bufH = smem + SM_AH + parity * 16384;
            const char* bufL = smem + SM_AL + parity * 16384;

            float acc[2][4][4];
#pragma unroll
            for (int m = 0; m < 2; m++)
#pragma unroll
                for (int nt = 0; nt < 4; nt++)
#pragma unroll
                    for (int j = 0; j < 4; j++) acc[m][nt][j] = 0.f;

#pragma unroll
            for (int ks = 0; ks < 8; ks++) {
                uint4 ah[2], al[2];
#pragma unroll
                for (int m = 0; m < 2; m++) {
                    const int g_ = rg * 2 + m;
                    ah[m] = ((const uint4*)(bufH + (g_ * 8 + ks) * 512))[pos];
                    al[m] = ((const uint4*)(bufL + (g_ * 8 + ks) * 512))[pos];
                }
                const uint4* Bp = (const uint4*)(smem + SM_B + (ks * 16 + cg * 4) * 512);
#pragma unroll
                for (int nt = 0; nt < 4; nt++) {
                    uint4 B = Bp[nt * 32 + lane];
#pragma unroll
                    for (int m = 0; m < 2; m++) {
                        mma_bf16(acc[m][nt], (const uint32_t*)&ah[m], B.x, B.y);
                        mma_bf16(acc[m][nt], (const uint32_t*)&ah[m], B.z, B.w);
                        mma_bf16(acc[m][nt], (const uint32_t*)&al[m], B.x, B.y);
                    }
                }
            }
            BAR_ARRIVE(parity ? BAR_EMPTY1 : BAR_EMPTY0);

            float* ob = out + (size_t)t * TILE_M * GD;
#pragma unroll
            for (int m = 0; m < 2; m++) {
                const int r0 = rg * 32 + m * 16 + (lane >> 2);
#pragma unroll
                for (int nt = 0; nt < 4; nt++) {
                    const int c = cg * 32 + nt * 8 + (lane & 3) * 2;
                    *(float2*)(ob + (size_t)r0 * GD + c) = make_float2(acc[m][nt][0], acc[m][nt][1]);
                    *(float2*)(ob + (size_t)(r0 + 8) * GD + c) = make_float2(acc[m][nt][2], acc[m][nt][3]);
                }
            }
        }
    }
}

// ---------------------------------------------------------------------------
extern "C" void kernel_launch(void* const* d_in, const int* in_sizes, int n_in,
                              void* d_out, int out_size) {
    const int*   archs    = (const int*)  d_in[0];
    const float* init_emb = (const float*)d_in[1];
    const float* op_emb   = (const float*)d_in[2];
    const float* xw       = (const float*)d_in[3];
    const float* xb       = (const float*)d_in[4];
    const float* w1       = (const float*)d_in[5];
    const float* w2       = (const float*)d_in[6];
    float* out = (float*)d_out;

    cudaFuncSetAttribute(gcn_main_kernel,
                         cudaFuncAttributeMaxDynamicSharedMemorySize, SMEM_BYTES);

    gcn_main_kernel<<<NCTAS, 512, SMEM_BYTES>>>(archs, init_emb, op_emb,
                                                xw, xb, w1, w2, out);
}

// round 16
// speedup vs baseline: 1.0039x; 1.0039x over previous
#include <cuda_runtime.h>
#include <cuda_bf16.h>
#include <cstdint>

// ---------------------------------------------------------------------------
// GCNArchEmbedder via mma.sync bf16 (HMMA), 3-pass hi/lo fp32 emulation.
// R16: single fused persistent kernel; prep operands (xw/w1/op_emb/init_emb/
//   xb) staged into smem first so table building is LDS-fed instead of
//   global-latency-bound. Pipeline identical to R13/R15.
// ---------------------------------------------------------------------------

#define NUM_PRIM   8
#define OPD        48
#define OPH        48
#define GD         128
#define ROWS       65536
#define TILE_M     64
#define NTILES     (ROWS / TILE_M)     // 1024
#define NCTAS      148
#define TPAD       132

typedef unsigned long long ull;
__device__ __forceinline__ ull pk2(float lo, float hi) {
    ull r; asm("mov.b64 %0, {%1, %2};" : "=l"(r) : "f"(lo), "f"(hi)); return r;
}
__device__ __forceinline__ void unpk2(float& lo, float& hi, ull v) {
    asm("mov.b64 {%0, %1}, %2;" : "=f"(lo), "=f"(hi) : "l"(v));
}
__device__ __forceinline__ ull add2(ull a, ull b) {
    ull r; asm("add.rn.f32x2 %0, %1, %2;" : "=l"(r) : "l"(a), "l"(b)); return r;
}
__device__ __forceinline__ ull mul2(ull a, ull b) {
    ull r; asm("mul.rn.f32x2 %0, %1, %2;" : "=l"(r) : "l"(a), "l"(b)); return r;
}
__device__ __forceinline__ void fma2(ull& d, ull a, ull b) {
    asm("fma.rn.f32x2 %0, %1, %2, %0;" : "+l"(d) : "l"(a), "l"(b));
}
// low half = first arg (k-even element)
__device__ __forceinline__ uint32_t bf16x2(float lo, float hi) {
    uint32_t r; asm("cvt.rn.bf16x2.f32 %0, %1, %2;" : "=r"(r) : "f"(hi), "f"(lo)); return r;
}
__device__ __forceinline__ float bf_lo(uint32_t u) { return __uint_as_float(u << 16); }
__device__ __forceinline__ float bf_hi(uint32_t u) { return __uint_as_float(u & 0xffff0000u); }

__device__ __forceinline__ void mma_bf16(float* d, const uint32_t* a,
                                         uint32_t b0, uint32_t b1) {
    asm volatile(
        "mma.sync.aligned.m16n8k16.row.col.f32.bf16.bf16.f32 "
        "{%0,%1,%2,%3}, {%4,%5,%6,%7}, {%8,%9}, {%0,%1,%2,%3};"
        : "+f"(d[0]), "+f"(d[1]), "+f"(d[2]), "+f"(d[3])
        : "r"(a[0]), "r"(a[1]), "r"(a[2]), "r"(a[3]), "r"(b0), "r"(b1));
}

// named-barrier produce/consume (count = all 512 threads)
#define BAR_SYNC(id)   asm volatile("bar.sync %0, 512;"   :: "r"(id) : "memory")
#define BAR_ARRIVE(id) asm volatile("bar.arrive %0, 512;" :: "r"(id) : "memory")
#define BAR_EMPTY0 1
#define BAR_EMPTY1 2
#define BAR_FULL0  3
#define BAR_FULL1  4

// ---------------------------------------------------------------------------
// smem byte layout:
//   AH[2]  0      (2 x 16384)   [g4][ks8][pos32] uint4, XOR-swizzled pos
//     staging overlay in AH/AL scratch (64KB):
//       Xs  (xw)      4608 floats @ 0
//       W1s (w1)      6144 floats @ 4608
//       OEs (op_emb)   384 floats @ 10752
//       IEs (init_emb) 192 floats @ 11136
//       XBs (xb)        48 floats @ 11328
//       Tsc/Ysc        864 floats @ 11376   (total 12240 floats = 48960 B)
//   AL[2]  32768  (2 x 16384)
//   B      65536  (65536)       [ks8][nt16][lane32] uint4 {b0h,b1h,b0l,b1l}
//   tab    131072 (9504)        18 x TPAD floats
// total 140576 B -> 1 CTA/SM.
// ---------------------------------------------------------------------------
#define SM_AH    0
#define SM_AL    32768
#define SM_B     65536
#define SM_TAB   131072
#define SMEM_BYTES 140576

__global__ void __launch_bounds__(512, 1)
gcn_main_kernel(const int* __restrict__ archs,
                const float* __restrict__ init_emb,
                const float* __restrict__ op_emb,
                const float* __restrict__ xw,
                const float* __restrict__ xb,
                const float* __restrict__ w1,
                const float* __restrict__ w2,
                float* __restrict__ out) {
    extern __shared__ char smem[];
    float* tab = (float*)(smem + SM_TAB);

    const int tid  = threadIdx.x;
    const int wid  = tid >> 5;
    const int lane = tid & 31;
    const bool consumer = (wid < 8);

    // ===================== fused prep (smem-staged operands) =================
    {
        float* Xs  = (float*)(smem + SM_AH);   // xw   [96][48]
        float* W1s = Xs + 4608;                // w1   [48][128]
        float* OEs = W1s + 6144;               // op_emb [8][48]
        float* IEs = OEs + 384;                // init_emb [2][96]
        float* XBs = IEs + 192;                // xb [48]
        float* Tsc = XBs + 48;                 // [8][2][48]
        float* Ysc = Tsc + 768;                // [2][48]

        // stage operands: coalesced float4 copies
        {
            float4* d;
            const float4* s;
            d = (float4*)Xs;  s = (const float4*)xw;
            for (int i = tid; i < 1152; i += 512) d[i] = s[i];
            d = (float4*)W1s; s = (const float4*)w1;
            for (int i = tid; i < 1536; i += 512) d[i] = s[i];
            if (tid < 96)  ((float4*)OEs)[tid] = ((const float4*)op_emb)[tid];
            else if (tid < 144) ((float4*)IEs)[tid - 96] = ((const float4*)init_emb)[tid - 96];
            else if (tid < 156) ((float4*)XBs)[tid - 144] = ((const float4*)xb)[tid - 144];
        }
        __syncthreads();

        // step 1: T (xb folded into which==0) and Y, all from smem
        for (int idx = tid; idx < 864; idx += 512) {
            if (idx < 768) {
                const int p = idx / 96;
                const int rem = idx % 96;
                const int which = rem / 48;
                const int h = rem % 48;
                float acc = (which == 0) ? XBs[h] : 0.f;
                const int db = which * OPD;
                for (int d = 0; d < OPD; d += 2) {
                    acc = fmaf(OEs[p * OPD + d],     Xs[(db + d) * OPH + h],     acc);
                    acc = fmaf(OEs[p * OPD + d + 1], Xs[(db + d + 1) * OPH + h], acc);
                }
                Tsc[(p * 2 + which) * OPH + h] = acc;
            } else {
                const int kk = (idx - 768) / 48;
                const int h = (idx - 768) % 48;
                float acc = XBs[h];
                for (int d = 0; d < 2 * OPD; d += 2) {
                    acc = fmaf(IEs[kk * 2 * OPD + d],     Xs[d * OPH + h],       acc);
                    acc = fmaf(IEs[kk * 2 * OPD + d + 1], Xs[(d + 1) * OPH + h], acc);
                }
                Ysc[kk * OPH + h] = acc;
            }
        }
        __syncthreads();

        // step 2: tab rows 0..7 = U0''[p] (incl. Uc), 8..15 = U1[p], 16..17 = H1init
        for (int idx = tid; idx < 18 * GD; idx += 512) {
            const int row = idx >> 7;
            const int f = idx & 127;
            const float* src = (row < 16) ? (Tsc + ((row & 7) * 2 + (row >> 3)) * OPH)
                                          : (Ysc + (row - 16) * OPH);
            float s0 = 0.f, s1 = 0.f;
            for (int h = 0; h < OPH; h += 2) {
                s0 = fmaf(src[h],     W1s[h * GD + f],       s0);
                s1 = fmaf(src[h + 1], W1s[(h + 1) * GD + f], s1);
            }
            tab[row * TPAD + f] = s0 + s1;
        }

        // step 3: W2 -> bf16 hi/lo mma B-fragments, written in-place
        uint4* Bsm = (uint4*)(smem + SM_B);
#pragma unroll
        for (int i = 0; i < 8; i++) {
            const int idx = tid + 512 * i;       // 0..4095
            const int bl  = idx & 31;
            const int nt  = (idx >> 5) & 15;
            const int ks  = idx >> 9;
            const int k0 = ks * 16 + (bl & 3) * 2;
            const int n  = nt * 8 + (bl >> 2);
            float w00 = w2[k0 * GD + n];
            float w01 = w2[(k0 + 1) * GD + n];
            float w10 = w2[(k0 + 8) * GD + n];
            float w11 = w2[(k0 + 9) * GD + n];
            uint32_t b0h = bf16x2(w00, w01);
            uint32_t b1h = bf16x2(w10, w11);
            uint32_t b0l = bf16x2(w00 - bf_lo(b0h), w01 - bf_hi(b0h));
            uint32_t b1l = bf16x2(w10 - bf_lo(b1h), w11 - bf_hi(b1h));
            Bsm[idx] = make_uint4(b0h, b1h, b0l, b1l);
        }
    }
    __syncthreads();

    // ===================== pipeline (verbatim R13) =====================
    // consumer constants
    const int rg = (wid >> 2) & 1;
    const int cg = wid & 3;
    const int pos = (lane & 28) | ((lane ^ (lane >> 3)) & 3);
    // producer constants
    const int ptid = tid - 256;
    const int prow = ptid & 63;
    const int pkq  = (ptid >> 6) & 3;

    // consumers pre-signal both buffers empty
    if (consumer) {
        BAR_ARRIVE(BAR_EMPTY0);
        BAR_ARRIVE(BAR_EMPTY1);
    }

    int parity = 0;
    for (int t = blockIdx.x; t < NTILES; t += NCTAS, parity ^= 1) {
        if (!consumer) {
            // ================= PRODUCE tile t into buf[parity] =================
            BAR_SYNC(parity ? BAR_EMPTY1 : BAR_EMPTY0);

            const int row = prow;
            const int g_  = row >> 4;
            const int r   = row & 7;
            const bool hiRole = ((row & 8) == 0);

            const int4* ap = (const int4*)(archs + ((size_t)t * TILE_M + row) * 16);
            int4 a0v = __ldg(ap), a1v = __ldg(ap + 1);
            int4 a2v = __ldg(ap + 2), a3v = __ldg(ap + 3);
            int pe[8] = {a0v.x, a0v.y, a0v.z, a0v.w, a1v.x, a1v.y, a1v.z, a1v.w};
            int oe[8] = {a2v.x, a2v.y, a2v.z, a2v.w, a3v.x, a3v.y, a3v.z, a3v.w};

            ull A2[4][6];
            float mmv[4];
#pragma unroll
            for (int s = 0; s < 4; s++) {
#pragma unroll
                for (int j = 0; j < 6; j++) {
                    float v = (pe[2 * s] == j ? 1.f : 0.f) + (pe[2 * s + 1] == j ? 1.f : 0.f);
                    A2[s][j] = pk2(v, v);
                }
                float c = 0.f;
#pragma unroll
                for (int e = 0; e < 8; e++) c += (pe[e] == s + 2) ? 1.f : 0.f;
                mmv[s] = c * 0.25f;
            }

            const float* qa0 = tab + oe[0] * TPAD;
            const float* qb0 = tab + (8 + oe[1]) * TPAD;
            const float* qa1 = tab + oe[2] * TPAD;
            const float* qb1 = tab + (8 + oe[3]) * TPAD;
            const float* qa2 = tab + oe[4] * TPAD;
            const float* qb2 = tab + (8 + oe[5]) * TPAD;
            const float* qa3 = tab + oe[6] * TPAD;
            const float* qb3 = tab + (8 + oe[7]) * TPAD;
            const float* p0 = tab + 16 * TPAD;
            const float* p1 = tab + 17 * TPAD;

            // quadcomp: one float4 batch -> TWO k-pair results (hi2/lo2 [0..1])
            auto quadcomp = [&](int k, uint32_t* hi2, uint32_t* lo2) {
                ulonglong2 H0 = *(const ulonglong2*)(p0 + k);
                ulonglong2 H1 = *(const ulonglong2*)(p1 + k);
                ulonglong2 QA0 = *(const ulonglong2*)(qa0 + k);
                ulonglong2 QB0 = *(const ulonglong2*)(qb0 + k);
                ulonglong2 QA1 = *(const ulonglong2*)(qa1 + k);
                ulonglong2 QB1 = *(const ulonglong2*)(qb1 + k);
                ulonglong2 QA2 = *(const ulonglong2*)(qa2 + k);
                ulonglong2 QB2 = *(const ulonglong2*)(qb2 + k);
                ulonglong2 QA3 = *(const ulonglong2*)(qa3 + k);
                ulonglong2 QB3 = *(const ulonglong2*)(qb3 + k);
                ull h[6][2];
                h[0][0] = H0.x; h[0][1] = H0.y;
                h[1][0] = H1.x; h[1][1] = H1.y;
                h[2][0] = add2(QA0.x, QB0.x); h[2][1] = add2(QA0.y, QB0.y);
                h[3][0] = add2(QA1.x, QB1.x); h[3][1] = add2(QA1.y, QB1.y);
                h[4][0] = add2(QA2.x, QB2.x); h[4][1] = add2(QA2.y, QB2.y);
                h[5][0] = add2(QA3.x, QB3.x); h[5][1] = add2(QA3.y, QB3.y);
#pragma unroll
                for (int u = 0; u < 2; u++) {
                    float s0 = 0.f, s1 = 0.f;
#pragma unroll
                    for (int s = 0; s < 4; s++) {
                        ull z = mul2(A2[s][0], h[0][u]);
                        fma2(z, A2[s][1], h[1][u]);
                        fma2(z, A2[s][2], h[2][u]);
                        fma2(z, A2[s][3], h[3][u]);
                        fma2(z, A2[s][4], h[4][u]);
                        fma2(z, A2[s][5], h[5][u]);
                        float zl, zh; unpk2(zl, zh, z);
                        zl = fmaxf(zl, 0.f);
                        zh = fmaxf(zh, 0.f);
                        s0 = fmaf(mmv[s], zl, s0);
                        s1 = fmaf(mmv[s], zh, s1);
                    }
                    hi2[u] = bf16x2(s0, s1);
                    lo2[u] = bf16x2(s0 - bf_lo(hi2[u]), s1 - bf_hi(hi2[u]));
                }
            };

            char* bufH = smem + SM_AH + parity * 16384;
            char* bufL = smem + SM_AL + parity * 16384;
#pragma unroll
            for (int kk = 0; kk < 2; kk++) {
                const int ks = pkq * 2 + kk;
                char* slotH = bufH + (g_ * 8 + ks) * 512;
                char* slotL = bufL + (g_ * 8 + ks) * 512;
#pragma unroll
                for (int jj = 0; jj < 2; jj++) {
                    uint32_t hA[2], lA[2], hC[2], lC[2];
                    quadcomp(ks * 16 + 4 * jj, hA, lA);
                    quadcomp(ks * 16 + 8 + 4 * jj, hC, lC);
#pragma unroll
                    for (int u = 0; u < 2; u++) {
                        const int j = 2 * jj + u;
                        uint32_t ohA = __shfl_xor_sync(0xffffffffu, hA[u], 8);
                        uint32_t ohC = __shfl_xor_sync(0xffffffffu, hC[u], 8);
                        uint32_t olA = __shfl_xor_sync(0xffffffffu, lA[u], 8);
                        uint32_t olC = __shfl_xor_sync(0xffffffffu, lC[u], 8);
                        const int p_ = r * 4 + (j ^ ((r >> 1) & 3));
                        if (hiRole) {
                            *(uint4*)(slotH + p_ * 16) = make_uint4(hA[u], ohA, hC[u], ohC);
                        } else {
                            *(uint4*)(slotL + p_ * 16) = make_uint4(olA, lA[u], olC, lC[u]);
                        }
                    }
                }
            }
            BAR_ARRIVE(parity ? BAR_FULL1 : BAR_FULL0);
        } else {
            // ================= CONSUME tile t from buf[parity] =================
            BAR_SYNC(parity ? BAR_FULL1 : BAR_FULL0);

            const char* bufH = smem + SM_AH + parity * 16384;
            const char* bufL = smem + SM_AL + parity * 16384;

            float acc[2][4][4];
#pragma unroll
            for (int m = 0; m < 2; m++)
#pragma unroll
                for (int nt = 0; nt < 4; nt++)
#pragma unroll
                    for (int j = 0; j < 4; j++) acc[m][nt][j] = 0.f;

#pragma unroll
            for (int ks = 0; ks < 8; ks++) {
                uint4 ah[2], al[2];
#pragma unroll
                for (int m = 0; m < 2; m++) {
                    const int g_ = rg * 2 + m;
                    ah[m] = ((const uint4*)(bufH + (g_ * 8 + ks) * 512))[pos];
                    al[m] = ((const uint4*)(bufL + (g_ * 8 + ks) * 512))[pos];
                }
                const uint4* Bp = (const uint4*)(smem + SM_B + (ks * 16 + cg * 4) * 512);
#pragma unroll
                for (int nt = 0; nt < 4; nt++) {
                    uint4 B = Bp[nt * 32 + lane];
#pragma unroll
                    for (int m = 0; m < 2; m++) {
                        mma_bf16(acc[m][nt], (const uint32_t*)&ah[m], B.x, B.y);
                        mma_bf16(acc[m][nt], (const uint32_t*)&ah[m], B.z, B.w);
                        mma_bf16(acc[m][nt], (const uint32_t*)&al[m], B.x, B.y);
                    }
                }
            }
            BAR_ARRIVE(parity ? BAR_EMPTY1 : BAR_EMPTY0);

            float* ob = out + (size_t)t * TILE_M * GD;
#pragma unroll
            for (int m = 0; m < 2; m++) {
                const int r0 = rg * 32 + m * 16 + (lane >> 2);
#pragma unroll
                for (int nt = 0; nt < 4; nt++) {
                    const int c = cg * 32 + nt * 8 + (lane & 3) * 2;
                    *(float2*)(ob + (size_t)r0 * GD + c) = make_float2(acc[m][nt][0], acc[m][nt][1]);
                    *(float2*)(ob + (size_t)(r0 + 8) * GD + c) = make_float2(acc[m][nt][2], acc[m][nt][3]);
                }
            }
        }
    }
}

// ---------------------------------------------------------------------------
extern "C" void kernel_launch(void* const* d_in, const int* in_sizes, int n_in,
                              void* d_out, int out_size) {
    const int*   archs    = (const int*)  d_in[0];
    const float* init_emb = (const float*)d_in[1];
    const float* op_emb   = (const float*)d_in[2];
    const float* xw       = (const float*)d_in[3];
    const float* xb       = (const float*)d_in[4];
    const float* w1       = (const float*)d_in[5];
    const float* w2       = (const float*)d_in[6];
    float* out = (float*)d_out;

    cudaFuncSetAttribute(gcn_main_kernel,
                         cudaFuncAttributeMaxDynamicSharedMemorySize, SMEM_BYTES);

    gcn_main_kernel<<<NCTAS, 512, SMEM_BYTES>>>(archs, init_emb, op_emb,
                                                xw, xb, w1, w2, out);
}

// round 17
// speedup vs baseline: 1.0479x; 1.0439x over previous
#include <cuda_runtime.h>
#include <cuda_bf16.h>
#include <cstdint>

// ---------------------------------------------------------------------------
// GCNArchEmbedder via mma.sync bf16 (HMMA), 3-pass hi/lo fp32 emulation.
// R17: R13 (best: persistent warp-specialized pipeline + wide prep kernel)
//   + Programmatic Dependent Launch: main kernel launches with
//   programmatic-stream-serialization and calls cudaGridDependencySynchronize()
//   only before touching prep outputs -> launch gap + init overlap prep.
// ---------------------------------------------------------------------------

#define NUM_PRIM   8
#define OPD        48
#define OPH        48
#define GD         128
#define ROWS       65536
#define TILE_M     64
#define NTILES     (ROWS / TILE_M)     // 1024
#define NCTAS      148
#define TPAD       132

// table rows: 0..7 U0''[p] (=U0+Uc), 8..15 U1[p], 16..17 H1init
__device__ float g_tab[18 * GD];
// W2 fragments: idx = (ks*16 + ntile)*32 + lane ; {b0hi, b1hi, b0lo, b1lo}
__device__ uint4 g_bfrag[4096];

typedef unsigned long long ull;
__device__ __forceinline__ ull pk2(float lo, float hi) {
    ull r; asm("mov.b64 %0, {%1, %2};" : "=l"(r) : "f"(lo), "f"(hi)); return r;
}
__device__ __forceinline__ void unpk2(float& lo, float& hi, ull v) {
    asm("mov.b64 {%0, %1}, %2;" : "=f"(lo), "=f"(hi) : "l"(v));
}
__device__ __forceinline__ ull add2(ull a, ull b) {
    ull r; asm("add.rn.f32x2 %0, %1, %2;" : "=l"(r) : "l"(a), "l"(b)); return r;
}
__device__ __forceinline__ ull mul2(ull a, ull b) {
    ull r; asm("mul.rn.f32x2 %0, %1, %2;" : "=l"(r) : "l"(a), "l"(b)); return r;
}
__device__ __forceinline__ void fma2(ull& d, ull a, ull b) {
    asm("fma.rn.f32x2 %0, %1, %2, %0;" : "+l"(d) : "l"(a), "l"(b));
}
// low half = first arg (k-even element)
__device__ __forceinline__ uint32_t bf16x2(float lo, float hi) {
    uint32_t r; asm("cvt.rn.bf16x2.f32 %0, %1, %2;" : "=r"(r) : "f"(hi), "f"(lo)); return r;
}
__device__ __forceinline__ float bf_lo(uint32_t u) { return __uint_as_float(u << 16); }
__device__ __forceinline__ float bf_hi(uint32_t u) { return __uint_as_float(u & 0xffff0000u); }

__device__ __forceinline__ void mma_bf16(float* d, const uint32_t* a,
                                         uint32_t b0, uint32_t b1) {
    asm volatile(
        "mma.sync.aligned.m16n8k16.row.col.f32.bf16.bf16.f32 "
        "{%0,%1,%2,%3}, {%4,%5,%6,%7}, {%8,%9}, {%0,%1,%2,%3};"
        : "+f"(d[0]), "+f"(d[1]), "+f"(d[2]), "+f"(d[3])
        : "r"(a[0]), "r"(a[1]), "r"(a[2]), "r"(a[3]), "r"(b0), "r"(b1));
}

__device__ __forceinline__ uint32_t smem_u32(const void* p) {
    uint32_t a;
    asm("{ .reg .u64 t; cvta.to.shared.u64 t, %1; cvt.u32.u64 %0, t; }" : "=r"(a) : "l"(p));
    return a;
}
__device__ __forceinline__ void cp_async16(uint32_t saddr, const void* g) {
    asm volatile("cp.async.cg.shared.global [%0], [%1], 16;" :: "r"(saddr), "l"(g) : "memory");
}

// named-barrier produce/consume (count = all 512 threads)
#define BAR_SYNC(id)   asm volatile("bar.sync %0, 512;"   :: "r"(id) : "memory")
#define BAR_ARRIVE(id) asm volatile("bar.arrive %0, 512;" :: "r"(id) : "memory")
#define BAR_EMPTY0 1
#define BAR_EMPTY1 2
#define BAR_FULL0  3
#define BAR_FULL1  4

// ---------------------------------------------------------------------------
// Prep kernel, <<<33, 256>>> (wide & shallow):
//   blocks 0..15 : (p, which) -> U0''[p] / U1[p]
//   block  16    : H1init rows
//   blocks 17..32: W2 fragment pack
// ---------------------------------------------------------------------------
__global__ void gcn_prep_kernel(const float* __restrict__ init_emb,
                                const float* __restrict__ op_emb,
                                const float* __restrict__ xw,
                                const float* __restrict__ xb,
                                const float* __restrict__ w1,
                                const float* __restrict__ w2) {
    const int b = blockIdx.x;
    const int t = threadIdx.x;

    if (b < 16) {                      // row (which*8 + p) of g_tab
        const int p = b >> 1, which = b & 1;
        __shared__ float T[OPH];
        if (t < OPH) {
            float s0 = 0.f, s1 = 0.f, s2 = 0.f, s3 = 0.f;
            const int db = which * OPD;
            for (int d = 0; d < OPD; d += 4) {
                s0 = fmaf(op_emb[p * OPD + d],     xw[(db + d) * OPH + t],     s0);
                s1 = fmaf(op_emb[p * OPD + d + 1], xw[(db + d + 1) * OPH + t], s1);
                s2 = fmaf(op_emb[p * OPD + d + 2], xw[(db + d + 2) * OPH + t], s2);
                s3 = fmaf(op_emb[p * OPD + d + 3], xw[(db + d + 3) * OPH + t], s3);
            }
            T[t] = (s0 + s1) + (s2 + s3);
        }
        __syncthreads();
        if (t < GD) {
            float s0 = 0.f, s1 = 0.f, u0 = 0.f, u1 = 0.f;
            for (int h = 0; h < OPH; h += 2) {
                float wa = w1[h * GD + t], wb = w1[(h + 1) * GD + t];
                s0 = fmaf(T[h],     wa, s0);
                s1 = fmaf(T[h + 1], wb, s1);
                u0 = fmaf(xb[h],     wa, u0);
                u1 = fmaf(xb[h + 1], wb, u1);
            }
            g_tab[(which * 8 + p) * GD + t] = s0 + s1 + (which == 0 ? (u0 + u1) : 0.f);
        }
    } else if (b == 16) {              // init rows
        __shared__ float Y[2][OPH];
        if (t < 96) {
            const int kk = t / 48, h = t % 48;
            float s0 = xb[h], s1 = 0.f, s2 = 0.f, s3 = 0.f;
            for (int d = 0; d < 2 * OPD; d += 4) {
                s0 = fmaf(init_emb[kk * 2 * OPD + d],     xw[d * OPH + h],       s0);
                s1 = fmaf(init_emb[kk * 2 * OPD + d + 1], xw[(d + 1) * OPH + h], s1);
                s2 = fmaf(init_emb[kk * 2 * OPD + d + 2], xw[(d + 2) * OPH + h], s2);
                s3 = fmaf(init_emb[kk * 2 * OPD + d + 3], xw[(d + 3) * OPH + h], s3);
            }
            Y[kk][h] = (s0 + s1) + (s2 + s3);
        }
        __syncthreads();
        const int kk = t >> 7, f = t & 127;
        float s0 = 0.f, s1 = 0.f;
        for (int h = 0; h < OPH; h += 2) {
            s0 = fmaf(Y[kk][h],     w1[h * GD + f],       s0);
            s1 = fmaf(Y[kk][h + 1], w1[(h + 1) * GD + f], s1);
        }
        g_tab[(16 + kk) * GD + f] = s0 + s1;
    } else {                           // W2 pack
        const int idx = (b - 17) * 256 + t;  // 0..4095
        const int lane = idx & 31;
        const int nt   = (idx >> 5) & 15;
        const int ks   = idx >> 9;
        const int k0 = ks * 16 + (lane & 3) * 2;
        const int n  = nt * 8 + (lane >> 2);
        float w00 = w2[k0 * GD + n];
        float w01 = w2[(k0 + 1) * GD + n];
        float w10 = w2[(k0 + 8) * GD + n];
        float w11 = w2[(k0 + 9) * GD + n];
        uint32_t b0h = bf16x2(w00, w01);
        uint32_t b1h = bf16x2(w10, w11);
        uint32_t b0l = bf16x2(w00 - bf_lo(b0h), w01 - bf_hi(b0h));
        uint32_t b1l = bf16x2(w10 - bf_lo(b1h), w11 - bf_hi(b1h));
        g_bfrag[idx] = make_uint4(b0h, b1h, b0l, b1l);
    }
}

// ---------------------------------------------------------------------------
// Persistent main kernel. smem byte layout:
//   AH[2]  0      (2 x 16384)   [g4][ks8][pos32] uint4, XOR-swizzled pos
//   AL[2]  32768  (2 x 16384)
//   B      65536  (65536)       [ks8][nt16][lane32] uint4 {b0h,b1h,b0l,b1l}
//   tab    131072 (9504)        18 x TPAD floats
// total 140576 B -> 1 CTA/SM.
// ---------------------------------------------------------------------------
#define SM_AH    0
#define SM_AL    32768
#define SM_B     65536
#define SM_TAB   131072
#define SMEM_BYTES 140576

__global__ void __launch_bounds__(512, 1)
gcn_main_kernel(const int* __restrict__ archs, float* __restrict__ out) {
    extern __shared__ char smem[];
    float* tab = (float*)(smem + SM_TAB);

    const int tid  = threadIdx.x;
    const int wid  = tid >> 5;
    const int lane = tid & 31;
    const bool consumer = (wid < 8);

    // ---- pre-dependency work (independent of prep outputs) ----
    // consumer constants
    const int rg = (wid >> 2) & 1;
    const int cg = wid & 3;
    const int pos = (lane & 28) | ((lane ^ (lane >> 3)) & 3);
    // producer constants
    const int ptid = tid - 256;
    const int prow = ptid & 63;
    const int pkq  = (ptid >> 6) & 3;

    if (consumer) {
        BAR_ARRIVE(BAR_EMPTY0);
        BAR_ARRIVE(BAR_EMPTY1);
    }

    // ---- wait for prep kernel's writes (PDL) ----
    cudaGridDependencySynchronize();

    // ---- one-time staging: B frags (cp.async) + tables ----
    {
        const uint32_t bsm = smem_u32(smem + SM_B);
#pragma unroll
        for (int i = 0; i < 8; i++)
            cp_async16(bsm + (tid + 512 * i) * 16, &g_bfrag[tid + 512 * i]);
        asm volatile("cp.async.commit_group;" ::: "memory");
        for (int idx = tid; idx < 18 * GD; idx += 512)
            tab[(idx >> 7) * TPAD + (idx & 127)] = g_tab[idx];
        asm volatile("cp.async.wait_group 0;" ::: "memory");
    }
    __syncthreads();

    int parity = 0;
    for (int t = blockIdx.x; t < NTILES; t += NCTAS, parity ^= 1) {
        if (!consumer) {
            // ================= PRODUCE tile t into buf[parity] =================
            BAR_SYNC(parity ? BAR_EMPTY1 : BAR_EMPTY0);

            const int row = prow;
            const int g_  = row >> 4;
            const int r   = row & 7;
            const bool hiRole = ((row & 8) == 0);

            const int4* ap = (const int4*)(archs + ((size_t)t * TILE_M + row) * 16);
            int4 a0v = __ldg(ap), a1v = __ldg(ap + 1);
            int4 a2v = __ldg(ap + 2), a3v = __ldg(ap + 3);
            int pe[8] = {a0v.x, a0v.y, a0v.z, a0v.w, a1v.x, a1v.y, a1v.z, a1v.w};
            int oe[8] = {a2v.x, a2v.y, a2v.z, a2v.w, a3v.x, a3v.y, a3v.z, a3v.w};

            ull A2[4][6];
            float mmv[4];
#pragma unroll
            for (int s = 0; s < 4; s++) {
#pragma unroll
                for (int j = 0; j < 6; j++) {
                    float v = (pe[2 * s] == j ? 1.f : 0.f) + (pe[2 * s + 1] == j ? 1.f : 0.f);
                    A2[s][j] = pk2(v, v);
                }
                float c = 0.f;
#pragma unroll
                for (int e = 0; e < 8; e++) c += (pe[e] == s + 2) ? 1.f : 0.f;
                mmv[s] = c * 0.25f;
            }

            const float* qa0 = tab + oe[0] * TPAD;
            const float* qb0 = tab + (8 + oe[1]) * TPAD;
            const float* qa1 = tab + oe[2] * TPAD;
            const float* qb1 = tab + (8 + oe[3]) * TPAD;
            const float* qa2 = tab + oe[4] * TPAD;
            const float* qb2 = tab + (8 + oe[5]) * TPAD;
            const float* qa3 = tab + oe[6] * TPAD;
            const float* qb3 = tab + (8 + oe[7]) * TPAD;
            const float* p0 = tab + 16 * TPAD;
            const float* p1 = tab + 17 * TPAD;

            // quadcomp: one float4 batch -> TWO k-pair results (hi2/lo2 [0..1])
            auto quadcomp = [&](int k, uint32_t* hi2, uint32_t* lo2) {
                ulonglong2 H0 = *(const ulonglong2*)(p0 + k);
                ulonglong2 H1 = *(const ulonglong2*)(p1 + k);
                ulonglong2 QA0 = *(const ulonglong2*)(qa0 + k);
                ulonglong2 QB0 = *(const ulonglong2*)(qb0 + k);
                ulonglong2 QA1 = *(const ulonglong2*)(qa1 + k);
                ulonglong2 QB1 = *(const ulonglong2*)(qb1 + k);
                ulonglong2 QA2 = *(const ulonglong2*)(qa2 + k);
                ulonglong2 QB2 = *(const ulonglong2*)(qb2 + k);
                ulonglong2 QA3 = *(const ulonglong2*)(qa3 + k);
                ulonglong2 QB3 = *(const ulonglong2*)(qb3 + k);
                ull h[6][2];
                h[0][0] = H0.x; h[0][1] = H0.y;
                h[1][0] = H1.x; h[1][1] = H1.y;
                h[2][0] = add2(QA0.x, QB0.x); h[2][1] = add2(QA0.y, QB0.y);
                h[3][0] = add2(QA1.x, QB1.x); h[3][1] = add2(QA1.y, QB1.y);
                h[4][0] = add2(QA2.x, QB2.x); h[4][1] = add2(QA2.y, QB2.y);
                h[5][0] = add2(QA3.x, QB3.x); h[5][1] = add2(QA3.y, QB3.y);
#pragma unroll
                for (int u = 0; u < 2; u++) {
                    float s0 = 0.f, s1 = 0.f;
#pragma unroll
                    for (int s = 0; s < 4; s++) {
                        ull z = mul2(A2[s][0], h[0][u]);
                        fma2(z, A2[s][1], h[1][u]);
                        fma2(z, A2[s][2], h[2][u]);
                        fma2(z, A2[s][3], h[3][u]);
                        fma2(z, A2[s][4], h[4][u]);
                        fma2(z, A2[s][5], h[5][u]);
                        float zl, zh; unpk2(zl, zh, z);
                        zl = fmaxf(zl, 0.f);
                        zh = fmaxf(zh, 0.f);
                        s0 = fmaf(mmv[s], zl, s0);
                        s1 = fmaf(mmv[s], zh, s1);
                    }
                    hi2[u] = bf16x2(s0, s1);
                    lo2[u] = bf16x2(s0 - bf_lo(hi2[u]), s1 - bf_hi(hi2[u]));
                }
            };

            char* bufH = smem + SM_AH + parity * 16384;
            char* bufL = smem + SM_AL + parity * 16384;
#pragma unroll
            for (int kk = 0; kk < 2; kk++) {
                const int ks = pkq * 2 + kk;
                char* slotH = bufH + (g_ * 8 + ks) * 512;
                char* slotL = bufL + (g_ * 8 + ks) * 512;
#pragma unroll
                for (int jj = 0; jj < 2; jj++) {
                    uint32_t hA[2], lA[2], hC[2], lC[2];
                    quadcomp(ks * 16 + 4 * jj, hA, lA);
                    quadcomp(ks * 16 + 8 + 4 * jj, hC, lC);
#pragma unroll
                    for (int u = 0; u < 2; u++) {
                        const int j = 2 * jj + u;
                        uint32_t ohA = __shfl_xor_sync(0xffffffffu, hA[u], 8);
                        uint32_t ohC = __shfl_xor_sync(0xffffffffu, hC[u], 8);
                        uint32_t olA = __shfl_xor_sync(0xffffffffu, lA[u], 8);
                        uint32_t olC = __shfl_xor_sync(0xffffffffu, lC[u], 8);
                        const int p_ = r * 4 + (j ^ ((r >> 1) & 3));
                        if (hiRole) {
                            *(uint4*)(slotH + p_ * 16) = make_uint4(hA[u], ohA, hC[u], ohC);
                        } else {
                            *(uint4*)(slotL + p_ * 16) = make_uint4(olA, lA[u], olC, lC[u]);
                        }
                    }
                }
            }
            BAR_ARRIVE(parity ? BAR_FULL1 : BAR_FULL0);
        } else {
            // ================= CONSUME tile t from buf[parity] =================
            BAR_SYNC(parity ? BAR_FULL1 : BAR_FULL0);

            const char* bufH = smem + SM_AH + parity * 16384;
            const char* bufL = smem + SM_AL + parity * 16384;

            float acc[2][4][4];
#pragma unroll
            for (int m = 0; m < 2; m++)
#pragma unroll
                for (int nt = 0; nt < 4; nt++)
#pragma unroll
                    for (int j = 0; j < 4; j++) acc[m][nt][j] = 0.f;

#pragma unroll
            for (int ks = 0; ks < 8; ks++) {
                uint4 ah[2], al[2];
#pragma unroll
                for (int m = 0; m < 2; m++) {
                    const int g_ = rg * 2 + m;
                    ah[m] = ((const uint4*)(bufH + (g_ * 8 + ks) * 512))[pos];
                    al[m] = ((const uint4*)(bufL + (g_ * 8 + ks) * 512))[pos];
                }
                const uint4* Bp = (const uint4*)(smem + SM_B + (ks * 16 + cg * 4) * 512);
#pragma unroll
                for (int nt = 0; nt < 4; nt++) {
                    uint4 B = Bp[nt * 32 + lane];
#pragma unroll
                    for (int m = 0; m < 2; m++) {
                        mma_bf16(acc[m][nt], (const uint32_t*)&ah[m], B.x, B.y);
                        mma_bf16(acc[m][nt], (const uint32_t*)&ah[m], B.z, B.w);
                        mma_bf16(acc[m][nt], (const uint32_t*)&al[m], B.x, B.y);
                    }
                }
            }
            BAR_ARRIVE(parity ? BAR_EMPTY1 : BAR_EMPTY0);

            float* ob = out + (size_t)t * TILE_M * GD;
#pragma unroll
            for (int m = 0; m < 2; m++) {
                const int r0 = rg * 32 + m * 16 + (lane >> 2);
#pragma unroll
                for (int nt = 0; nt < 4; nt++) {
                    const int c = cg * 32 + nt * 8 + (lane & 3) * 2;
                    *(float2*)(ob + (size_t)r0 * GD + c) = make_float2(acc[m][nt][0], acc[m][nt][1]);
                    *(float2*)(ob + (size_t)(r0 + 8) * GD + c) = make_float2(acc[m][nt][2], acc[m][nt][3]);
                }
            }
        }
    }
}

// ---------------------------------------------------------------------------
extern "C" void kernel_launch(void* const* d_in, const int* in_sizes, int n_in,
                              void* d_out, int out_size) {
    const int*   archs    = (const int*)  d_in[0];
    const float* init_emb = (const float*)d_in[1];
    const float* op_emb   = (const float*)d_in[2];
    const float* xw       = (const float*)d_in[3];
    const float* xb       = (const float*)d_in[4];
    const float* w1       = (const float*)d_in[5];
    const float* w2       = (const float*)d_in[6];
    float* out = (float*)d_out;

    cudaFuncSetAttribute(gcn_main_kernel,
                         cudaFuncAttributeMaxDynamicSharedMemorySize, SMEM_BYTES);

    gcn_prep_kernel<<<33, 256>>>(init_emb, op_emb, xw, xb, w1, w2);

    // main kernel with Programmatic Dependent Launch: starts while prep is
    // finishing; cudaGridDependencySynchronize() inside gates the staging.
    cudaLaunchConfig_t cfg = {};
    cfg.gridDim = dim3(NCTAS);
    cfg.blockDim = dim3(512);
    cfg.dynamicSmemBytes = SMEM_BYTES;
    cfg.stream = 0;
    cudaLaunchAttribute attrs[1];
    attrs[0].id = cudaLaunchAttributeProgrammaticStreamSerialization;
    attrs[0].val.programmaticStreamSerializationAllowed = 1;
    cfg.attrs = attrs;
    cfg.numAttrs = 1;
    cudaLaunchKernelEx(&cfg, gcn_main_kernel, archs, out);
}